// round 2
// baseline (speedup 1.0000x reference)
#include <cuda_runtime.h>

typedef unsigned long long u64;

static constexpr int D = 1024;
static constexpr int K = 32;
static constexpr int TILE_R = 256;   // rows per block, 1 thread per row
static constexpr int NT = 256;

__device__ float g_G[K * K];
__device__ float g_C[K * K];

__device__ __forceinline__ u64 pack2(float lo, float hi) {
    u64 r;
    asm("mov.b64 %0, {%1, %2};" : "=l"(r) : "f"(lo), "f"(hi));
    return r;
}
__device__ __forceinline__ float2 unpack2(u64 v) {
    float2 r;
    asm("mov.b64 {%0, %1}, %2;" : "=f"(r.x), "=f"(r.y) : "l"(v));
    return r;
}
__device__ __forceinline__ void ffma2(u64& d, u64 a, u64 b) {
    asm("fma.rn.f32x2 %0, %1, %2, %0;" : "+l"(d) : "l"(a), "l"(b));
}

// ---------------- G = V V^T (32 x 32) ----------------
__global__ void gram_kernel(const float* __restrict__ V) {
    int k1 = blockIdx.x;             // 32 blocks
    int w = threadIdx.x >> 5;        // 8 warps
    int lane = threadIdx.x & 31;
    #pragma unroll
    for (int i = 0; i < 4; i++) {
        int k2 = w * 4 + i;
        float s = 0.f;
        #pragma unroll
        for (int j = 0; j < D; j += 128) {
            float4 a = *(const float4*)(V + k1 * D + j + lane * 4);
            float4 b = *(const float4*)(V + k2 * D + j + lane * 4);
            s += a.x * b.x + a.y * b.y + a.z * b.z + a.w * b.w;
        }
        #pragma unroll
        for (int o = 16; o; o >>= 1) s += __shfl_down_sync(0xffffffffu, s, o);
        if (lane == 0) g_G[k1 * K + k2] = s;
    }
}

// ---------------- C = (I+U)^{-1} diag(beta) ----------------
__global__ void prepc_kernel() {
    __shared__ float G[K * K];
    __shared__ float beta[K];
    int t = threadIdx.x;             // 32 threads, t = output column c
    for (int i = t; i < K * K; i += 32) G[i] = g_G[i];
    __syncwarp();
    beta[t] = 1.f / G[t * K + t];
    __syncwarp();
    float x[K];
    int c = t;
    for (int j = 0; j < K; j++) x[j] = 0.f;
    x[c] = 1.f;
    for (int j = c - 1; j >= 0; j--) {       // (I+U) x = e_c, U[j][m]=beta_j*G[j][m], m>j
        float s = 0.f;
        for (int m = j + 1; m <= c; m++) s += beta[j] * G[j * K + m] * x[m];
        x[j] = -s;
    }
    for (int j = 0; j < K; j++) g_C[j * K + c] = x[j] * beta[c];
}

// ---------------- fused: out = h - ((h V^T) C) V ----------------
__global__ __launch_bounds__(NT, 2) void fused_kernel(
    const float* __restrict__ H, const float* __restrict__ V,
    float* __restrict__ OUT)
{
    __shared__ float s_buf[64 * 36];     // phase A: Vt[64][36]; phase B: Vs[32][68]
    __shared__ float s_C[K * K];

    const int t = threadIdx.x;
    const int row = blockIdx.x * TILE_R + t;

    for (int i = t; i < K * K; i += NT) s_C[i] = g_C[i];

    // ======== Phase A: p[32] = h_row . V^T ========
    u64 acc[16];
    #pragma unroll
    for (int i = 0; i < 16; i++) acc[i] = 0ULL;

    for (int dc = 0; dc < D; dc += 64) {
        __syncthreads();
        #pragma unroll
        for (int i = 0; i < 2; i++) {            // load V chunk transposed: Vt[d][k]
            int q = i * NT + t;
            int k = q >> 4, f4 = q & 15;
            float4 vv = *(const float4*)(V + k * D + dc + f4 * 4);
            s_buf[(f4 * 4 + 0) * 36 + k] = vv.x;
            s_buf[(f4 * 4 + 1) * 36 + k] = vv.y;
            s_buf[(f4 * 4 + 2) * 36 + k] = vv.z;
            s_buf[(f4 * 4 + 3) * 36 + k] = vv.w;
        }
        __syncthreads();
        const float* hrow = H + row * D + dc;
        #pragma unroll 2
        for (int d2 = 0; d2 < 16; d2++) {
            float4 hv = *(const float4*)(hrow + d2 * 4);
            const float* hs = (const float*)&hv;
            #pragma unroll
            for (int j = 0; j < 4; j++) {
                u64 hh = pack2(hs[j], hs[j]);
                const float* vtd = &s_buf[(d2 * 4 + j) * 36];
                #pragma unroll
                for (int kk = 0; kk < 8; kk++) {
                    float4 v4 = *(const float4*)(vtd + kk * 4);   // broadcast LDS.128
                    const u64* vp = (const u64*)&v4;
                    ffma2(acc[kk * 2 + 0], hh, vp[0]);
                    ffma2(acc[kk * 2 + 1], hh, vp[1]);
                }
            }
        }
    }

    // ======== w[32] = p . C ========
    float p[K];
    #pragma unroll
    for (int i = 0; i < 16; i++) {
        float2 f = unpack2(acc[i]);
        p[2 * i] = f.x;
        p[2 * i + 1] = f.y;
    }
    u64 wacc[16];
    #pragma unroll
    for (int i = 0; i < 16; i++) wacc[i] = 0ULL;
    #pragma unroll
    for (int j = 0; j < K; j++) {
        u64 pj = pack2(p[j], p[j]);
        #pragma unroll
        for (int kk = 0; kk < 8; kk++) {
            float4 c4 = *(const float4*)(&s_C[j * K + kk * 4]);
            const u64* cp = (const u64*)&c4;
            ffma2(wacc[kk * 2 + 0], pj, cp[0]);
            ffma2(wacc[kk * 2 + 1], pj, cp[1]);
        }
    }
    u64 wp[K];     // wp[k] = (w[k], w[k]) packed
    #pragma unroll
    for (int i = 0; i < 16; i++) {
        float2 f = unpack2(wacc[i]);
        wp[2 * i] = pack2(f.x, f.x);
        wp[2 * i + 1] = pack2(f.y, f.y);
    }

    // ======== Phase B: out_row = h_row - w . V ========
    for (int dc = 0; dc < D; dc += 64) {
        __syncthreads();
        #pragma unroll
        for (int i = 0; i < 2; i++) {            // load V chunk natural: Vs[k][d]
            int q = i * NT + t;
            int k = q >> 4, f4 = q & 15;
            *(float4*)(&s_buf[k * 68 + f4 * 4]) =
                *(const float4*)(V + k * D + dc + f4 * 4);
        }
        __syncthreads();
        #pragma unroll 2
        for (int d4 = 0; d4 < 16; d4++) {
            u64 c2[2] = {0ULL, 0ULL};
            #pragma unroll
            for (int k = 0; k < K; k++) {
                float4 v4 = *(const float4*)(&s_buf[k * 68 + d4 * 4]);  // broadcast
                const u64* vp = (const u64*)&v4;
                ffma2(c2[0], wp[k], vp[0]);
                ffma2(c2[1], wp[k], vp[1]);
            }
            float2 lo = unpack2(c2[0]);
            float2 hi = unpack2(c2[1]);
            float4 hv = *(const float4*)(H + row * D + dc + d4 * 4);
            float4 o;
            o.x = hv.x - lo.x;
            o.y = hv.y - lo.y;
            o.z = hv.z - hi.x;
            o.w = hv.w - hi.y;
            *(float4*)(OUT + row * D + dc + d4 * 4) = o;
        }
    }
}

extern "C" void kernel_launch(void* const* d_in, const int* in_sizes, int n_in,
                              void* d_out, int out_size) {
    const float* H = (const float*)d_in[0];   // node_feat [65536, 1024]
    const float* V = (const float*)d_in[1];   // V [32, 1024]
    float* OUT = (float*)d_out;
    const int N = in_sizes[0] / D;            // 65536

    gram_kernel<<<K, 256>>>(V);
    prepc_kernel<<<1, 32>>>();
    fused_kernel<<<N / TILE_R, NT>>>(H, V, OUT);
}